// round 16
// baseline (speedup 1.0000x reference)
#include <cuda_runtime.h>
#include <cstdint>

#define BATCH 4096

// ---- 32KB chunks (8192 floats). TMA serves L3 (0..4095); LDG serves the rest ----
#define CHUNK_FLOATS 8192
#define C3_END 4096
#define C2_END 5120
#define C1_END 5376
#define NCHUNK 5440
#define CHUNK_BYTES 32768
#define NLDG 1344               // L2+L1+L0 chunks

#define NB_CE 296               // 2 CTAs/SM x 148 SMs; one exact wave
#define NSTAGE 3
#define MAXKT 14                // max TMA chunks per CTA
#define DEP_PER_CTA 14

__device__ float g_part[NB_CE];
__device__ float g_depA[NB_CE];
__device__ int   g_done;        // zero-init; self-resets each replay

__device__ __forceinline__ float vec_expsum(float4 v) {
    return __expf(v.x) + __expf(v.y) + __expf(v.z) + __expf(v.w);
}
__device__ __forceinline__ float warp_sum(float s) {
    #pragma unroll
    for (int off = 16; off; off >>= 1)
        s += __shfl_xor_sync(0xffffffffu, s, off);
    return s;
}
__device__ __forceinline__ uint32_t smem_u32(const void* p) {
    return (uint32_t)__cvta_generic_to_shared(p);
}
__device__ __forceinline__ void mbar_init(uint32_t a) {
    asm volatile("mbarrier.init.shared.b64 [%0], 1;" :: "r"(a) : "memory");
}
__device__ __forceinline__ void mbar_wait(uint32_t a, int parity) {
    asm volatile(
        "{\n\t.reg .pred P;\n\t"
        "W%=:\n\t"
        "mbarrier.try_wait.parity.acquire.cta.shared::cta.b64 P, [%0], %1, 0x989680;\n\t"
        "@P bra D%=;\n\t"
        "bra W%=;\n\t"
        "D%=:\n\t}"
        :: "r"(a), "r"(parity) : "memory");
}
__device__ __forceinline__ void bulk_load(uint32_t dst, const void* src,
                                          uint32_t bytes, uint32_t mbar) {
    asm volatile("mbarrier.arrive.expect_tx.shared.b64 _, [%0], %1;"
                 :: "r"(mbar), "r"(bytes) : "memory");
    asm volatile(
        "cp.async.bulk.shared::cluster.global.mbarrier::complete_tx::bytes "
        "[%0], [%1], %2, [%3];"
        :: "r"(dst), "l"(src), "r"(bytes), "r"(mbar) : "memory");
}

__global__ void __launch_bounds__(256)
fused_kernel(const float* __restrict__ o0, const float* __restrict__ o1,
             const float* __restrict__ o2, const float* __restrict__ o3,
             const int* __restrict__ targets,
             const int* __restrict__ p0, const int* __restrict__ p1,
             const int* __restrict__ p2, const int* __restrict__ p3,
             const int* __restrict__ v01, const int* __restrict__ v12,
             const int* __restrict__ v23,
             float* __restrict__ out) {
    extern __shared__ float stage[];              // NSTAGE * 8192 floats
    __shared__ unsigned long long mbar_s[NSTAGE];
    __shared__ float sws[2][8];                   // TMA L3 warp partials (by k&1)
    __shared__ float sws2[8];                     // LDG L2 warp partials
    __shared__ float swr[8];
    __shared__ int   tpref[MAXKT];                // L3 target indices
    __shared__ bool  is_last;

    const int bid = blockIdx.x;
    const int tid = threadIdx.x;
    const int wid = tid >> 5;
    const int lid = tid & 31;

    float acc = 0.0f;

    const int n_tma = (C3_END - bid + NB_CE - 1) / NB_CE;   // 13 or 14
    const int n_ldg = (NLDG   - bid + NB_CE - 1) / NB_CE;   // 4 or 5

    uint32_t mbf[NSTAGE], stg[NSTAGE];
    #pragma unroll
    for (int s = 0; s < NSTAGE; s++) {
        mbf[s] = smem_u32(&mbar_s[s]);
        stg[s] = smem_u32(&stage[s * CHUNK_FLOATS]);
    }
    if (tid == 0) {
        #pragma unroll
        for (int s = 0; s < NSTAGE; s++) mbar_init(mbf[s]);
    }
    __syncthreads();

    if (tid == 0) {
        #pragma unroll
        for (int kp = 0; kp < NSTAGE; kp++)
            bulk_load(stg[kp], o3 + (size_t)(bid + kp * NB_CE) * CHUNK_FLOATS,
                      CHUNK_BYTES, mbf[kp]);
    }

    // parallel L3 target-index prefetch (one lane per chunk)
    if (tid < n_tma) tpref[tid] = targets[(bid + tid * NB_CE) * 4 + 3];

    // dep spread over all CTAs (warp 0), hidden under pipeline fill
    {
        float cnt = 0.0f;
        if (tid < DEP_PER_CTA) {
            const int i = bid * DEP_PER_CTA + tid;
            if (i < BATCH) {
                const int a = p0[i], b = p1[i], cc = p2[i], e = p3[i];
                cnt += (v01[a * 512   + b ] == 0) ? 1.0f : 0.0f;
                cnt += (v12[b * 2048  + cc] == 0) ? 1.0f : 0.0f;
                cnt += (v23[cc * 8192 + e ] == 0) ? 1.0f : 0.0f;
            }
        }
        if (wid == 0) {
            cnt = warp_sum(cnt);
            if (lid == 0) g_depA[bid] = cnt;
        }
    }

    // ---- main loop: TMA L3 chunk per iter; LDG chunk every 3rd iter ----
    for (int k = 0; k < n_tma; k++) {
        const int s = k % NSTAGE;
        const int par = (k / NSTAGE) & 1;
        const int pb = k & 1;

        // LDG chunk due this iteration? (j = k/3 at k = 3j+1)
        const int j = k / 3;
        const bool ldue = ((k % 3) == 1) && (j < n_ldg);
        int cl = 0;
        const float* srcl = nullptr;
        float4 lv[8];
        if (ldue) {
            cl = C3_END + bid + j * NB_CE;
            const float4* lbase;
            if (cl < C2_END) {
                srcl = o2 + (size_t)(cl - C3_END) * CHUNK_FLOATS;
                lbase = (const float4*)srcl + wid * 256;          // 8 x (m*32+lid)
                #pragma unroll
                for (int m = 0; m < 8; m++) lv[m] = __ldcs(lbase + m * 32 + lid);
            } else if (cl < C1_END) {
                srcl = o1 + (size_t)(cl - C2_END) * CHUNK_FLOATS;
                const int h = lid >> 4, sl = lid & 15;
                lbase = (const float4*)srcl + wid * 256 + h * 128; // 8 x (m*16+sl)
                #pragma unroll
                for (int m = 0; m < 8; m++) lv[m] = __ldcs(lbase + m * 16 + sl);
            } else {
                srcl = o0 + (size_t)(cl - C1_END) * CHUNK_FLOATS;
                const int g = lid >> 2, q = lid & 3;
                lbase = (const float4*)srcl + wid * 256 + g * 32;  // 8 x (m*4+q)
                #pragma unroll
                for (int m = 0; m < 8; m++) lv[m] = __ldcs(lbase + m * 4 + q);
            }
        }

        mbar_wait(mbf[s], par);   // LDG batch flies during this wait

        // ---- consume TMA L3 chunk from smem ----
        const float*  sf = stage + s * CHUNK_FLOATS;
        {
            const float4* wp = (const float4*)sf + wid * 256;
            float a0 = 0.f, a1 = 0.f, a2 = 0.f, a3 = 0.f;
            #pragma unroll
            for (int kk = 0; kk < 2; kk++) {
                a0 += vec_expsum(wp[(kk * 4 + 0) * 32 + lid]);
                a1 += vec_expsum(wp[(kk * 4 + 1) * 32 + lid]);
                a2 += vec_expsum(wp[(kk * 4 + 2) * 32 + lid]);
                a3 += vec_expsum(wp[(kk * 4 + 3) * 32 + lid]);
            }
            float sw = warp_sum((a0 + a1) + (a2 + a3));
            if (lid == 0) sws[pb][wid] = sw;
        }

        // ---- consume LDG registers ----
        if (ldue) {
            if (cl < C2_END) {
                float a0 = vec_expsum(lv[0]) + vec_expsum(lv[4]);
                float a1 = vec_expsum(lv[1]) + vec_expsum(lv[5]);
                float a2 = vec_expsum(lv[2]) + vec_expsum(lv[6]);
                float a3 = vec_expsum(lv[3]) + vec_expsum(lv[7]);
                float sw = warp_sum((a0 + a1) + (a2 + a3));
                if (lid == 0) sws2[wid] = sw;
            } else if (cl < C1_END) {
                const int h = lid >> 4, sl = lid & 15;
                const int rl = wid * 2 + h;
                int tIdx = 0;
                if (sl == 0) tIdx = targets[((cl - C2_END) * 16 + rl) * 4 + 1];
                float a0 = 0.f, a1 = 0.f;
                #pragma unroll
                for (int m = 0; m < 8; m += 2) { a0 += vec_expsum(lv[m]);
                                                 a1 += vec_expsum(lv[m + 1]); }
                float sv = a0 + a1;
                #pragma unroll
                for (int off = 8; off; off >>= 1)
                    sv += __shfl_xor_sync(0xffffffffu, sv, off);
                if (sl == 0) acc += __logf(sv) - __ldcs(srcl + rl * 512 + tIdx);
            } else {
                const int g = lid >> 2, q = lid & 3;
                const int rl = wid * 8 + g;
                int tIdx = 0;
                if (q == 0) tIdx = targets[((cl - C1_END) * 64 + rl) * 4 + 0];
                float a0 = 0.f, a1 = 0.f;
                #pragma unroll
                for (int m = 0; m < 8; m += 2) { a0 += vec_expsum(lv[m]);
                                                 a1 += vec_expsum(lv[m + 1]); }
                float sv = a0 + a1;
                #pragma unroll
                for (int off = 2; off; off >>= 1)
                    sv += __shfl_xor_sync(0xffffffffu, sv, off);
                if (q == 0) acc += __logf(sv) - __ldcs(srcl + rl * 128 + tIdx);
            }
        }

        __syncthreads();   // stage-s reads done; sws/sws2 published

        // parallel tails: t0 = L3 combine + refill; t32 = L2-LDG combine
        if (tid == 0) {
            float ssum = ((sws[pb][0] + sws[pb][1]) + (sws[pb][2] + sws[pb][3])) +
                         ((sws[pb][4] + sws[pb][5]) + (sws[pb][6] + sws[pb][7]));
            acc += __logf(ssum) - sf[tpref[k]];
            const int kn = k + NSTAGE;
            if (kn < n_tma) {
                asm volatile("fence.proxy.async.shared::cta;" ::: "memory");
                bulk_load(stg[s], o3 + (size_t)(bid + kn * NB_CE) * CHUNK_FLOATS,
                          CHUNK_BYTES, mbf[s]);
            }
        }
        if (tid == 32 && ldue && cl < C2_END) {
            const int rb = (cl - C3_END) * 4;
            #pragma unroll
            for (int jj = 0; jj < 4; jj++) {
                float rs = sws2[2 * jj] + sws2[2 * jj + 1];
                const int t = targets[(rb + jj) * 4 + 2];
                acc += __logf(rs) - __ldcs(srcl + jj * 2048 + t);
            }
        }
    }

    // ---- per-CTA combine ----
    __syncthreads();
    float ws = warp_sum(acc);
    if (lid == 0) swr[wid] = ws;
    __syncthreads();
    if (tid == 0) {
        float a = 0.0f;
        #pragma unroll
        for (int w = 0; w < 8; w++) a += swr[w];
        g_part[bid] = a;
    }

    // ---- last-block finalize ----
    if (tid == 0) {
        __threadfence();
        int ticket = atomicAdd(&g_done, 1);
        is_last = (ticket == NB_CE - 1);
        if (is_last) g_done = 0;
    }
    __syncthreads();

    if (is_last) {
        float ce = 0.0f, dep = 0.0f;
        for (int i = tid; i < NB_CE; i += 256) {
            ce  += __ldcg(&g_part[i]);
            dep += __ldcg(&g_depA[i]);
        }
        ce  = warp_sum(ce);
        dep = warp_sum(dep);
        __syncthreads();
        if (lid == 0) { swr[wid] = ce; sws2[wid] = dep; }
        __syncthreads();
        if (tid == 0) {
            float ce_sum = 0.0f, depcnt = 0.0f;
            #pragma unroll
            for (int w = 0; w < 8; w++) { ce_sum += swr[w]; depcnt += sws2[w]; }

            const float E_MINUS_1 = 1.7182818284590452f;
            const float inv_b = 1.0f / (float)BATCH;
            float ce_total  = ce_sum * inv_b;
            float dep_total = E_MINUS_1 * depcnt * inv_b;
            out[0] = 0.5f * ce_total + 0.5f * dep_total;
            out[1] = ce_total;
            out[2] = dep_total;
        }
    }
}

extern "C" void kernel_launch(void* const* d_in, const int* in_sizes, int n_in,
                              void* d_out, int out_size) {
    const float* o0 = (const float*)d_in[0];
    const float* o1 = (const float*)d_in[1];
    const float* o2 = (const float*)d_in[2];
    const float* o3 = (const float*)d_in[3];
    const int* targets = (const int*)d_in[4];
    const int* p0 = (const int*)d_in[5];
    const int* p1 = (const int*)d_in[6];
    const int* p2 = (const int*)d_in[7];
    const int* p3 = (const int*)d_in[8];
    const int* v01 = (const int*)d_in[9];
    const int* v12 = (const int*)d_in[10];
    const int* v23 = (const int*)d_in[11];
    float* out = (float*)d_out;

    const size_t smem = NSTAGE * CHUNK_BYTES;   // 98304 B
    cudaFuncSetAttribute(fused_kernel,
                         cudaFuncAttributeMaxDynamicSharedMemorySize, (int)smem);
    fused_kernel<<<NB_CE, 256, smem>>>(o0, o1, o2, o3, targets,
                                       p0, p1, p2, p3, v01, v12, v23, out);
}

// round 17
// speedup vs baseline: 1.1195x; 1.1195x over previous
#include <cuda_runtime.h>
#include <cstdint>

#define BATCH 4096

// ---- uniform 32KB chunks (8192 floats) over concatenated logits ----
#define CHUNK_FLOATS 8192
#define CHUNK_BYTES  32768
#define HALF_FLOATS  4096
#define HALF_BYTES   16384
#define C3_END 4096              // L3: 1 row/chunk
#define C2_END 5120              // L2: 4 rows/chunk
#define C1_END 5376              // L1: 16 rows/chunk
#define NCHUNK 5440              // L0: 64 rows/chunk

#define NB_CE 296                // 2 CTAs/SM x 148 SMs; one exact wave
#define NSTAGE 3
#define MAXK 19                  // ceil(5440/296)
#define DEP_PER_CTA 14           // ceil(4096/296)

__device__ float g_part[NB_CE];
__device__ float g_depA[NB_CE];
__device__ int   g_done;         // zero-init; self-resets each replay

__device__ __forceinline__ float vec_expsum(float4 v) {
    return __expf(v.x) + __expf(v.y) + __expf(v.z) + __expf(v.w);
}
__device__ __forceinline__ float warp_sum(float s) {
    #pragma unroll
    for (int off = 16; off; off >>= 1)
        s += __shfl_xor_sync(0xffffffffu, s, off);
    return s;
}
__device__ __forceinline__ uint32_t smem_u32(const void* p) {
    return (uint32_t)__cvta_generic_to_shared(p);
}
__device__ __forceinline__ void mbar_init(uint32_t a) {
    asm volatile("mbarrier.init.shared.b64 [%0], 1;" :: "r"(a) : "memory");
}
__device__ __forceinline__ void mbar_wait(uint32_t a, int parity) {
    asm volatile(
        "{\n\t.reg .pred P;\n\t"
        "W%=:\n\t"
        "mbarrier.try_wait.parity.acquire.cta.shared::cta.b64 P, [%0], %1, 0x989680;\n\t"
        "@P bra D%=;\n\t"
        "bra W%=;\n\t"
        "D%=:\n\t}"
        :: "r"(a), "r"(parity) : "memory");
}
__device__ __forceinline__ void bulk_copy(uint32_t dst, const void* src,
                                          uint32_t bytes, uint32_t mbar) {
    asm volatile(
        "cp.async.bulk.shared::cluster.global.mbarrier::complete_tx::bytes "
        "[%0], [%1], %2, [%3];"
        :: "r"(dst), "l"(src), "r"(bytes), "r"(mbar) : "memory");
}
// 32KB stage fill as TWO 16KB bulk requests -> 2x TMA request concurrency.
__device__ __forceinline__ void bulk_load_split(uint32_t dst, const float* src,
                                                uint32_t mbar) {
    asm volatile("mbarrier.arrive.expect_tx.shared.b64 _, [%0], %1;"
                 :: "r"(mbar), "r"((uint32_t)CHUNK_BYTES) : "memory");
    bulk_copy(dst,              src,               HALF_BYTES, mbar);
    bulk_copy(dst + HALF_BYTES, src + HALF_FLOATS, HALF_BYTES, mbar);
}

__global__ void __launch_bounds__(256)
fused_kernel(const float* __restrict__ o0, const float* __restrict__ o1,
             const float* __restrict__ o2, const float* __restrict__ o3,
             const int* __restrict__ targets,
             const int* __restrict__ p0, const int* __restrict__ p1,
             const int* __restrict__ p2, const int* __restrict__ p3,
             const int* __restrict__ v01, const int* __restrict__ v12,
             const int* __restrict__ v23,
             float* __restrict__ out) {
    extern __shared__ float stage[];              // NSTAGE * 8192 floats
    __shared__ unsigned long long mbar_s[NSTAGE];
    __shared__ float sws[2][8];                   // double-buffered warp partials
    __shared__ float swr[8];
    __shared__ int   tpref[MAXK * 4];             // prefetched L3/L2 target indices
    __shared__ bool  is_last;

    const int bid = blockIdx.x;
    const int tid = threadIdx.x;
    const int wid = tid >> 5;
    const int lid = tid & 31;

    float acc = 0.0f;

    uint32_t mb[NSTAGE], stg[NSTAGE];
    #pragma unroll
    for (int s = 0; s < NSTAGE; s++) {
        mb[s]  = smem_u32(&mbar_s[s]);
        stg[s] = smem_u32(&stage[s * CHUNK_FLOATS]);
    }
    if (tid == 0) {
        #pragma unroll
        for (int s = 0; s < NSTAGE; s++) mbar_init(mb[s]);
    }
    __syncthreads();

    auto src_of = [&](int c) -> const float* {
        if (c < C3_END) return o3 + (size_t)c * CHUNK_FLOATS;
        if (c < C2_END) return o2 + (size_t)(c - C3_END) * CHUNK_FLOATS;
        if (c < C1_END) return o1 + (size_t)(c - C2_END) * CHUNK_FLOATS;
        return o0 + (size_t)(c - C1_END) * CHUNK_FLOATS;
    };

    if (tid == 0) {
        #pragma unroll
        for (int kp = 0; kp < NSTAGE; kp++) {
            int c = bid + kp * NB_CE;
            if (c < NCHUNK) bulk_load_split(stg[kp], src_of(c), mb[kp]);
        }
    }

    // ---- parallel target prefetch: thread k handles its own chunk k ----
    if (tid < MAXK) {
        const int c = bid + tid * NB_CE;
        if (c < C3_END) {
            tpref[tid * 4] = targets[c * 4 + 3];
        } else if (c < C2_END) {
            const int rb = (c - C3_END) * 4;
            tpref[tid * 4 + 0] = targets[(rb + 0) * 4 + 2];
            tpref[tid * 4 + 1] = targets[(rb + 1) * 4 + 2];
            tpref[tid * 4 + 2] = targets[(rb + 2) * 4 + 2];
            tpref[tid * 4 + 3] = targets[(rb + 3) * 4 + 2];
        }
    }

    // ---- dep spread over ALL CTAs: one sample/thread, warp 0 only ----
    {
        float cnt = 0.0f;
        if (tid < DEP_PER_CTA) {
            const int i = bid * DEP_PER_CTA + tid;
            if (i < BATCH) {
                const int a = p0[i], b = p1[i], cc = p2[i], e = p3[i];
                cnt += (v01[a * 512   + b ] == 0) ? 1.0f : 0.0f;
                cnt += (v12[b * 2048  + cc] == 0) ? 1.0f : 0.0f;
                cnt += (v23[cc * 8192 + e ] == 0) ? 1.0f : 0.0f;
            }
        }
        if (wid == 0) {
            cnt = warp_sum(cnt);
            if (lid == 0) g_depA[bid] = cnt;
        }
    }

    // ---- main pipelined loop ----
    for (int k = 0, c = bid; c < NCHUNK; k++, c += NB_CE) {
        const int s = k % NSTAGE;
        const int parity = (k / NSTAGE) & 1;
        const int pb = k & 1;
        mbar_wait(mb[s], parity);

        const float*  sf = stage + s * CHUNK_FLOATS;
        const float4* st = (const float4*)sf;

        if (c < C2_END) {
            // L3/L2: per-warp partial over its 1024-float segment.
            const float4* wp = st + wid * 256;
            float a0 = 0.f, a1 = 0.f, a2 = 0.f, a3 = 0.f;
            #pragma unroll
            for (int kk = 0; kk < 2; kk++) {
                a0 += vec_expsum(wp[(kk * 4 + 0) * 32 + lid]);
                a1 += vec_expsum(wp[(kk * 4 + 1) * 32 + lid]);
                a2 += vec_expsum(wp[(kk * 4 + 2) * 32 + lid]);
                a3 += vec_expsum(wp[(kk * 4 + 3) * 32 + lid]);
            }
            float sw = warp_sum((a0 + a1) + (a2 + a3));
            if (lid == 0) sws[pb][wid] = sw;
        } else if (c < C1_END) {
            // L1: 16 rows of 512; half-warp per row.
            const int h  = lid >> 4;
            const int sl = lid & 15;
            const int rl = wid * 2 + h;
            int tIdx = 0;
            if (sl == 0) tIdx = targets[((c - C2_END) * 16 + rl) * 4 + 1];
            const float4* wp = st + wid * 256 + h * 128;
            float a0 = 0.f, a1 = 0.f;
            #pragma unroll
            for (int kk = 0; kk < 8; kk += 2) {
                a0 += vec_expsum(wp[(kk + 0) * 16 + sl]);
                a1 += vec_expsum(wp[(kk + 1) * 16 + sl]);
            }
            float sv = a0 + a1;
            #pragma unroll
            for (int off = 8; off; off >>= 1)
                sv += __shfl_xor_sync(0xffffffffu, sv, off);
            if (sl == 0) acc += __logf(sv) - sf[rl * 512 + tIdx];
        } else {
            // L0: 64 rows of 128; lane-quad per row.
            const int g = lid >> 2;
            const int q = lid & 3;
            const int rl = wid * 8 + g;
            int tIdx = 0;
            if (q == 0) tIdx = targets[((c - C1_END) * 64 + rl) * 4 + 0];
            const float4* gp = st + wid * 256 + g * 32;
            float a0 = 0.f, a1 = 0.f;
            #pragma unroll
            for (int kk = 0; kk < 8; kk += 2) {
                a0 += vec_expsum(gp[(kk + 0) * 4 + q]);
                a1 += vec_expsum(gp[(kk + 1) * 4 + q]);
            }
            float sv = a0 + a1;
            #pragma unroll
            for (int off = 2; off; off >>= 1)
                sv += __shfl_xor_sync(0xffffffffu, sv, off);
            if (q == 0) acc += __logf(sv) - sf[rl * 128 + tIdx];
        }

        __syncthreads();   // all reads of stage s complete; sws[pb] published

        if (tid == 0) {
            if (c < C3_END) {
                float ssum = ((sws[pb][0] + sws[pb][1]) + (sws[pb][2] + sws[pb][3])) +
                             ((sws[pb][4] + sws[pb][5]) + (sws[pb][6] + sws[pb][7]));
                acc += __logf(ssum) - sf[tpref[k * 4]];      // smem idx, no LDG
            } else if (c < C2_END) {
                #pragma unroll
                for (int j = 0; j < 4; j++) {
                    float rs = sws[pb][2 * j] + sws[pb][2 * j + 1];
                    acc += __logf(rs) - sf[j * 2048 + tpref[k * 4 + j]];
                }
            }
            const int cn = c + NSTAGE * NB_CE;
            if (cn < NCHUNK) {
                asm volatile("fence.proxy.async.shared::cta;" ::: "memory");
                bulk_load_split(stg[s], src_of(cn), mb[s]);
            }
        }
    }

    // ---- per-CTA combine ----
    float ws = warp_sum(acc);
    __syncthreads();
    if (lid == 0) swr[wid] = ws;
    __syncthreads();
    if (tid == 0) {
        float a = 0.0f;
        #pragma unroll
        for (int w = 0; w < 8; w++) a += swr[w];
        g_part[bid] = a;
    }

    // ---- last-block finalize ----
    if (tid == 0) {
        __threadfence();
        int ticket = atomicAdd(&g_done, 1);
        is_last = (ticket == NB_CE - 1);
        if (is_last) g_done = 0;
    }
    __syncthreads();

    if (is_last) {
        float ce = 0.0f, dep = 0.0f;
        for (int i = tid; i < NB_CE; i += 256) {
            ce  += __ldcg(&g_part[i]);
            dep += __ldcg(&g_depA[i]);
        }
        ce  = warp_sum(ce);
        dep = warp_sum(dep);
        __syncthreads();
        if (lid == 0) { swr[wid] = ce; sws[0][wid] = dep; }
        __syncthreads();
        if (tid == 0) {
            float ce_sum = 0.0f, depcnt = 0.0f;
            #pragma unroll
            for (int w = 0; w < 8; w++) { ce_sum += swr[w]; depcnt += sws[0][w]; }

            const float E_MINUS_1 = 1.7182818284590452f;
            const float inv_b = 1.0f / (float)BATCH;
            float ce_total  = ce_sum * inv_b;
            float dep_total = E_MINUS_1 * depcnt * inv_b;
            out[0] = 0.5f * ce_total + 0.5f * dep_total;
            out[1] = ce_total;
            out[2] = dep_total;
        }
    }
}

extern "C" void kernel_launch(void* const* d_in, const int* in_sizes, int n_in,
                              void* d_out, int out_size) {
    const float* o0 = (const float*)d_in[0];
    const float* o1 = (const float*)d_in[1];
    const float* o2 = (const float*)d_in[2];
    const float* o3 = (const float*)d_in[3];
    const int* targets = (const int*)d_in[4];
    const int* p0 = (const int*)d_in[5];
    const int* p1 = (const int*)d_in[6];
    const int* p2 = (const int*)d_in[7];
    const int* p3 = (const int*)d_in[8];
    const int* v01 = (const int*)d_in[9];
    const int* v12 = (const int*)d_in[10];
    const int* v23 = (const int*)d_in[11];
    float* out = (float*)d_out;

    const size_t smem = NSTAGE * CHUNK_BYTES;   // 98304 B
    cudaFuncSetAttribute(fused_kernel,
                         cudaFuncAttributeMaxDynamicSharedMemorySize, (int)smem);
    fused_kernel<<<NB_CE, 256, smem>>>(o0, o1, o2, o3, targets,
                                       p0, p1, p2, p3, v01, v12, v23, out);
}